// round 10
// baseline (speedup 1.0000x reference)
#include <cuda_runtime.h>
#include <cstdint>

// QConv2d, two balanced kernels; this round: occupancy unlock.
//   new_rho[(c,P),(c',P')] = sum_{e,e'} cc[c,e] cc[c',e'] A[(e,P),(e',P')]
//   cc[c,e]=uc[c,e+2],  A = L rho L^T,  L = I2 (x) ux (x) uy (separable).
// K1: scratch = L rho            grid 1024 (b x 32-col slice), 128 thr, <=64 regs
// K2: out = expand(A L^T)        grid 2048 (b x 8-P-row slice), 128 thr, <=64 regs
// Both __launch_bounds__(128, 8): 8 CTAs/SM = 32 warps resident.

typedef unsigned long long u64;

__device__ float g_scratch[256 * 128 * 128];   // 16 MB intermediate

__device__ __forceinline__ float4 f4fma(float c, float4 a, float4 acc) {
    acc.x = fmaf(c, a.x, acc.x); acc.y = fmaf(c, a.y, acc.y);
    acc.z = fmaf(c, a.z, acc.z); acc.w = fmaf(c, a.w, acc.w);
    return acc;
}
__device__ __forceinline__ float4 f4mul(float c, float4 a) {
    float4 r; r.x = c * a.x; r.y = c * a.y; r.z = c * a.z; r.w = c * a.w;
    return r;
}

// ======================= K1: left transform =======================
#define ST1 36   // 32 + 4 pad (16B-aligned rows)

__global__ __launch_bounds__(128, 8)
void qconv2d_k1(const float* __restrict__ rho,
                const float* __restrict__ ux,
                const float* __restrict__ uy) {
    __shared__ float A[128 * ST1];
    __shared__ float sux[64], suy[64];

    const int t  = threadIdx.x;
    const int b  = blockIdx.x >> 2;
    const int cb = blockIdx.x & 3;

    if (t < 64) { sux[t] = ux[t]; suy[t] = uy[t]; }

    const int cq = t & 7;        // column quad within 32-col slice
    const int gi = t >> 3;       // (e,i) group 0..15

    // Pass A: contract uy over j, input straight from GMEM (coalesced).
    const float* rb = rho + (size_t)b * 16384 + cb * 32 + 4 * cq;
    float4 in[8];
#pragma unroll
    for (int j = 0; j < 8; j++)
        in[j] = *(const float4*)(rb + (size_t)(gi * 8 + j) * 128);
    __syncthreads();             // tables ready
#pragma unroll
    for (int k = 0; k < 8; k++) {
        float4 acc = f4mul(suy[k * 8], in[0]);
#pragma unroll
        for (int j = 1; j < 8; j++) acc = f4fma(suy[k * 8 + j], in[j], acc);
        *(float4*)&A[(gi * 8 + k) * ST1 + 4 * cq] = acc;
    }
    __syncthreads();

    // Pass B: contract ux over i, write scratch (coalesced).
    const int kj = (t >> 3) & 7;
    const int e  = t >> 6;
    float* sb = g_scratch + (size_t)b * 16384 + cb * 32 + 4 * cq;
    float4 in2[8];
#pragma unroll
    for (int i = 0; i < 8; i++)
        in2[i] = *(float4*)&A[(e * 64 + i * 8 + kj) * ST1 + 4 * cq];
#pragma unroll
    for (int k = 0; k < 8; k++) {
        float4 acc = f4mul(sux[k * 8], in2[0]);
#pragma unroll
        for (int i = 1; i < 8; i++) acc = f4fma(sux[k * 8 + i], in2[i], acc);
        *(float4*)(sb + (size_t)(e * 64 + k * 8 + kj) * 128) = acc;
    }
}

// ============ K2: right transform + channel expansion ============
#define ST2 132  // 128 + 4 pad

__global__ __launch_bounds__(128, 8)
void qconv2d_k2(const float* __restrict__ ux,
                const float* __restrict__ uy,
                const float* __restrict__ uc,
                float* __restrict__ out) {
    __shared__ float A[16 * ST2];           // 16 local rows (2 e' x 8 P-rows)
    __shared__ float sux[64], suy[64], scc[8];

    const int t  = threadIdx.x;
    const int b  = blockIdx.x >> 3;
    const int P0 = (blockIdx.x & 7) * 8;

    if (t < 64) { sux[t] = ux[t]; suy[t] = uy[t]; }
    else if (t < 72) { int m = t - 64; scc[m] = uc[(m >> 1) * 4 + 2 + (m & 1)]; }

    // ---- Load slice coalescedly: local row r(0..15) -> global (r>>3)*64+P0+(r&7).
    {
        int r  = t >> 3;
        int q0 = t & 7;
        int gr = ((r >> 3) << 6) + P0 + (r & 7);
        const float4* src = (const float4*)(g_scratch + (size_t)b * 16384 + (size_t)gr * 128);
        float4 v[4];
#pragma unroll
        for (int k = 0; k < 4; k++) v[k] = src[q0 + 8 * k];
#pragma unroll
        for (int k = 0; k < 4; k++)
            *(float4*)&A[r * ST2 + 4 * (q0 + 8 * k)] = v[k];
    }
    __syncthreads();

    // ---- Pass 3 (cols, uy over j'): cols cg*8+j' -> cg*8+kj', in place.
#pragma unroll 1
    for (int it = 0; it < 2; it++) {
        int task = t + 128 * it;
        int r = task & 15, cg = task >> 4;   // cg = (e',i') 0..15
        float4 p = *(float4*)&A[r * ST2 + cg * 8];
        float4 q = *(float4*)&A[r * ST2 + cg * 8 + 4];
        float v0 = p.x, v1 = p.y, v2 = p.z, v3 = p.w;
        float v4 = q.x, v5 = q.y, v6 = q.z, v7 = q.w;
        float o[8];
#pragma unroll
        for (int k = 0; k < 8; k++) {
            float acc = suy[k * 8] * v0;
            acc = fmaf(suy[k * 8 + 1], v1, acc); acc = fmaf(suy[k * 8 + 2], v2, acc);
            acc = fmaf(suy[k * 8 + 3], v3, acc); acc = fmaf(suy[k * 8 + 4], v4, acc);
            acc = fmaf(suy[k * 8 + 5], v5, acc); acc = fmaf(suy[k * 8 + 6], v6, acc);
            acc = fmaf(suy[k * 8 + 7], v7, acc);
            o[k] = acc;
        }
        *(float4*)&A[r * ST2 + cg * 8]     = make_float4(o[0], o[1], o[2], o[3]);
        *(float4*)&A[r * ST2 + cg * 8 + 4] = make_float4(o[4], o[5], o[6], o[7]);
    }
    __syncthreads();

    // ---- Pass 4 (cols, ux over i'): 64 tasks (threads 64..127 idle; short pass).
    if (t < 64) {
        int r = t & 15, e2 = (t >> 4) & 1, kjq = t >> 5;   // kjq 0..1
        int base = r * ST2 + e2 * 64 + 4 * kjq;
        float4 in[8];
#pragma unroll
        for (int i = 0; i < 8; i++) in[i] = *(float4*)&A[base + 8 * i];
#pragma unroll
        for (int k = 0; k < 8; k++) {
            float4 acc = f4mul(sux[k * 8], in[0]);
#pragma unroll
            for (int i = 1; i < 8; i++) acc = f4fma(sux[k * 8 + i], in[i], acc);
            *(float4*)&A[base + 8 * k] = acc;
        }
    }
    __syncthreads();

    // ---- Epilogue: each (p, col-quad) read ONCE; emit all 16 (c,c') blocks.
    const float c00 = scc[0], c01 = scc[1], c10 = scc[2], c11 = scc[3];
    const float c20 = scc[4], c21 = scc[5], c30 = scc[6], c31 = scc[7];
    {
        int q = t & 15, p = t >> 4;          // q: col quad 0..15, p: 0..7
        float4 a00 = *(float4*)&A[p * ST2 + 4 * q];
        float4 a01 = *(float4*)&A[p * ST2 + 64 + 4 * q];
        float4 a10 = *(float4*)&A[(8 + p) * ST2 + 4 * q];
        float4 a11 = *(float4*)&A[(8 + p) * ST2 + 64 + 4 * q];
        float* ob = out + (size_t)b * 65536 + (size_t)(P0 + p) * 256 + 4 * q;
#pragma unroll
        for (int cp = 0; cp < 4; cp++) {
            const float k0 = scc[2 * cp], k1 = scc[2 * cp + 1];
            float4 v0 = f4fma(k1, a01, f4mul(k0, a00));
            float4 v1 = f4fma(k1, a11, f4mul(k0, a10));
            float4 w;
            w = f4fma(c01, v1, f4mul(c00, v0));
            *(float4*)(ob + (size_t)(0 * 64) * 256 + cp * 64) = w;
            w = f4fma(c11, v1, f4mul(c10, v0));
            *(float4*)(ob + (size_t)(1 * 64) * 256 + cp * 64) = w;
            w = f4fma(c21, v1, f4mul(c20, v0));
            *(float4*)(ob + (size_t)(2 * 64) * 256 + cp * 64) = w;
            w = f4fma(c31, v1, f4mul(c30, v0));
            *(float4*)(ob + (size_t)(3 * 64) * 256 + cp * 64) = w;
        }
    }
}

extern "C" void kernel_launch(void* const* d_in, const int* in_sizes, int n_in,
                              void* d_out, int out_size) {
    const float* rho = (const float*)d_in[0];   // [256,128,128]
    const float* ux  = (const float*)d_in[1];   // [8,8]
    const float* uy  = (const float*)d_in[2];   // [8,8]
    const float* uc  = (const float*)d_in[3];   // [4,4]
    float* out = (float*)d_out;                 // [256,256,256]

    qconv2d_k1<<<1024, 128>>>(rho, ux, uy);
    qconv2d_k2<<<2048, 128>>>(ux, uy, uc, out);
}

// round 12
// speedup vs baseline: 1.2774x; 1.2774x over previous
#include <cuda_runtime.h>
#include <cstdint>

// QConv2d, two balanced kernels, COLUMN transforms first (order swap).
//   new_rho[(c,P),(c',P')] = sum_{e,e'} cc[c,e] cc[c',e'] A[(e,P),(e',P')]
//   cc[c,e]=uc[c,e+2],  A = L (rho L^T),  L = I2 (x) ux (x) uy.
// K1 (grid 1024 = b x 32-row slice, 128 thr): col passes (j', i') per-row.
// K2 (grid 512 = b x 32-P'-pair slice, 256 thr): row passes (j, i) per-col
//     + channel-expansion epilogue. Tile = cols {P'0..+31} U {64+P'0..+31}.
// R12 fix: K1 j'-pass now covers all 512 (row, octet) tasks (R11 did 128).

typedef unsigned long long u64;

__device__ float g_scratch[256 * 128 * 128];   // 16 MB: rho L^T

__device__ __forceinline__ float4 f4fma(float c, float4 a, float4 acc) {
    acc.x = fmaf(c, a.x, acc.x); acc.y = fmaf(c, a.y, acc.y);
    acc.z = fmaf(c, a.z, acc.z); acc.w = fmaf(c, a.w, acc.w);
    return acc;
}
__device__ __forceinline__ float4 f4mul(float c, float4 a) {
    float4 r; r.x = c * a.x; r.y = c * a.y; r.z = c * a.z; r.w = c * a.w;
    return r;
}

// ======================= K1: right (column) transform =======================
#define ST1 132   // 132 = 4*33, 33 odd -> 8-lane phases conflict-free

__global__ __launch_bounds__(128)
void qconv2d_k1(const float* __restrict__ rho,
                const float* __restrict__ ux,
                const float* __restrict__ uy) {
    __shared__ float A[32 * ST1];
    __shared__ float sux[64], suy[64];

    const int t  = threadIdx.x;
    const int b  = blockIdx.x >> 2;
    const int R0 = (blockIdx.x & 3) * 32;

    if (t < 64) { sux[t] = ux[t]; suy[t] = uy[t]; }

    // ---- Load 32 rows x 128 cols, coalesced (4 x 128B per warp inst).
    {
        const int q0 = t & 7;            // f4 index low
        const int r0 = t >> 3;           // 0..15
        const float* rb = rho + (size_t)b * 16384 + (size_t)(R0) * 128;
#pragma unroll
        for (int k = 0; k < 2; k++) {
            int r = r0 + 16 * k;
#pragma unroll
            for (int m = 0; m < 4; m++) {
                float4 v = *(const float4*)(rb + (size_t)r * 128 + 4 * (q0 + 8 * m));
                *(float4*)&A[r * ST1 + 4 * (q0 + 8 * m)] = v;
            }
        }
    }
    __syncthreads();

    // ---- Col pass j' (uy): octet-local, per row. 32 rows x 16 octets = 512 tasks.
#pragma unroll 1
    for (int it = 0; it < 4; it++) {
        int task = t + 128 * it;
        int r = task & 31, o = task >> 5;    // o = 0..15
        float4 p = *(float4*)&A[r * ST1 + o * 8];
        float4 q = *(float4*)&A[r * ST1 + o * 8 + 4];
        float v0 = p.x, v1 = p.y, v2 = p.z, v3 = p.w;
        float v4 = q.x, v5 = q.y, v6 = q.z, v7 = q.w;
        float oo[8];
#pragma unroll
        for (int k = 0; k < 8; k++) {
            float acc = suy[k * 8] * v0;
            acc = fmaf(suy[k * 8 + 1], v1, acc); acc = fmaf(suy[k * 8 + 2], v2, acc);
            acc = fmaf(suy[k * 8 + 3], v3, acc); acc = fmaf(suy[k * 8 + 4], v4, acc);
            acc = fmaf(suy[k * 8 + 5], v5, acc); acc = fmaf(suy[k * 8 + 6], v6, acc);
            acc = fmaf(suy[k * 8 + 7], v7, acc);
            oo[k] = acc;
        }
        *(float4*)&A[r * ST1 + o * 8]     = make_float4(oo[0], oo[1], oo[2], oo[3]);
        *(float4*)&A[r * ST1 + o * 8 + 4] = make_float4(oo[4], oo[5], oo[6], oo[7]);
    }
    __syncthreads();

    // ---- Col pass i' (ux): cols e2*64 + i*8 + (4kq..+3), per row. Task (r,e2,kq).
    {
        int r = t & 31, e2 = (t >> 5) & 1, kq = t >> 6;   // kq 0..1
        int base = r * ST1 + e2 * 64 + 4 * kq;
        float4 in[8];
#pragma unroll
        for (int i = 0; i < 8; i++) in[i] = *(float4*)&A[base + 8 * i];
#pragma unroll
        for (int k = 0; k < 8; k++) {
            float4 acc = f4mul(sux[k * 8], in[0]);
#pragma unroll
            for (int i = 1; i < 8; i++) acc = f4fma(sux[k * 8 + i], in[i], acc);
            *(float4*)&A[base + 8 * k] = acc;
        }
    }
    __syncthreads();

    // ---- Store 32 rows coalescedly to scratch.
    {
        const int q0 = t & 7;
        const int r0 = t >> 3;
        float* sb = g_scratch + (size_t)b * 16384 + (size_t)(R0) * 128;
#pragma unroll
        for (int k = 0; k < 2; k++) {
            int r = r0 + 16 * k;
#pragma unroll
            for (int m = 0; m < 4; m++) {
                float4 v = *(float4*)&A[r * ST1 + 4 * (q0 + 8 * m)];
                *(float4*)(sb + (size_t)r * 128 + 4 * (q0 + 8 * m)) = v;
            }
        }
    }
}

// ============ K2: left (row) transform + channel expansion ============
#define ST2 68   // 68 = 4*17, 17 odd -> conflict-free phases

__global__ __launch_bounds__(256)
void qconv2d_k2(const float* __restrict__ ux,
                const float* __restrict__ uy,
                const float* __restrict__ uc,
                float* __restrict__ out) {
    __shared__ float A[128 * ST2];       // 128 rows x 64 local cols (+pad)
    __shared__ float sux[64], suy[64], scc[8];

    const int t   = threadIdx.x;
    const int b   = blockIdx.x >> 1;
    const int Pp0 = (blockIdx.x & 1) * 32;   // P' slice base

    if (t < 64) { sux[t] = ux[t]; suy[t] = uy[t]; }
    else if (t < 72) { int m = t - 64; scc[m] = uc[(m >> 1) * 4 + 2 + (m & 1)]; }

    // ---- Load tile: local col seg*32 + 4q0 <- global col seg*64 + Pp0 + 4q0.
    {
        const int q0  = t & 7;           // 0..7
        const int seg = (t >> 3) & 1;    // e' half
        const int r0  = t >> 4;          // 0..15
        const float* src = g_scratch + (size_t)b * 16384 + seg * 64 + Pp0 + 4 * q0;
#pragma unroll
        for (int k = 0; k < 8; k++) {
            int r = r0 + 16 * k;
            float4 v = *(const float4*)(src + (size_t)r * 128);
            *(float4*)&A[r * ST2 + seg * 32 + 4 * q0] = v;
        }
    }
    __syncthreads();

    // ---- Row pass j (uy): rows gi*8+j -> gi*8+kj, per col quad. Task (gi, colq).
    {
        int colq = t & 15, gi = t >> 4;  // gi = (e,i) 0..15
        float4 in[8];
#pragma unroll
        for (int j = 0; j < 8; j++) in[j] = *(float4*)&A[(gi * 8 + j) * ST2 + 4 * colq];
#pragma unroll
        for (int k = 0; k < 8; k++) {
            float4 acc = f4mul(suy[k * 8], in[0]);
#pragma unroll
            for (int j = 1; j < 8; j++) acc = f4fma(suy[k * 8 + j], in[j], acc);
            *(float4*)&A[(gi * 8 + k) * ST2 + 4 * colq] = acc;
        }
    }
    __syncthreads();

    // ---- Row pass i (ux): rows e*64+i*8+kj -> e*64+k*8+kj. Task (e,kj,colq).
    {
        int colq = t & 15, rem = t >> 4;
        int kj = rem & 7, e = rem >> 3;
        float4 in[8];
#pragma unroll
        for (int i = 0; i < 8; i++)
            in[i] = *(float4*)&A[(e * 64 + i * 8 + kj) * ST2 + 4 * colq];
#pragma unroll
        for (int k = 0; k < 8; k++) {
            float4 acc = f4mul(sux[k * 8], in[0]);
#pragma unroll
            for (int i = 1; i < 8; i++) acc = f4fma(sux[k * 8 + i], in[i], acc);
            *(float4*)&A[(e * 64 + k * 8 + kj) * ST2 + 4 * colq] = acc;
        }
    }
    __syncthreads();

    // ---- Epilogue: each (P, P'-quad) read ONCE; emit all 16 (c,cp) blocks.
    const float c00 = scc[0], c01 = scc[1], c10 = scc[2], c11 = scc[3];
    const float c20 = scc[4], c21 = scc[5], c30 = scc[6], c31 = scc[7];
#pragma unroll 1
    for (int it = 0; it < 2; it++) {
        int task = t + 256 * it;
        int pq = task & 7, P = task >> 3;     // pq: P'-quad 0..7, P: 0..63
        float4 a00 = *(float4*)&A[P * ST2 + 4 * pq];            // e=0, e'=0
        float4 a01 = *(float4*)&A[P * ST2 + 32 + 4 * pq];       // e=0, e'=1
        float4 a10 = *(float4*)&A[(64 + P) * ST2 + 4 * pq];     // e=1, e'=0
        float4 a11 = *(float4*)&A[(64 + P) * ST2 + 32 + 4 * pq];
        float* ob = out + (size_t)b * 65536 + (size_t)P * 256 + Pp0 + 4 * pq;
#pragma unroll
        for (int cp = 0; cp < 4; cp++) {
            const float k0 = scc[2 * cp], k1 = scc[2 * cp + 1];
            float4 v0 = f4fma(k1, a01, f4mul(k0, a00));
            float4 v1 = f4fma(k1, a11, f4mul(k0, a10));
            float4 w;
            w = f4fma(c01, v1, f4mul(c00, v0));
            *(float4*)(ob + (size_t)(0 * 64) * 256 + cp * 64) = w;
            w = f4fma(c11, v1, f4mul(c10, v0));
            *(float4*)(ob + (size_t)(1 * 64) * 256 + cp * 64) = w;
            w = f4fma(c21, v1, f4mul(c20, v0));
            *(float4*)(ob + (size_t)(2 * 64) * 256 + cp * 64) = w;
            w = f4fma(c31, v1, f4mul(c30, v0));
            *(float4*)(ob + (size_t)(3 * 64) * 256 + cp * 64) = w;
        }
    }
}

extern "C" void kernel_launch(void* const* d_in, const int* in_sizes, int n_in,
                              void* d_out, int out_size) {
    const float* rho = (const float*)d_in[0];   // [256,128,128]
    const float* ux  = (const float*)d_in[1];   // [8,8]
    const float* uy  = (const float*)d_in[2];   // [8,8]
    const float* uc  = (const float*)d_in[3];   // [4,4]
    float* out = (float*)d_out;                 // [256,256,256]

    qconv2d_k1<<<1024, 128>>>(rho, ux, uy);
    qconv2d_k2<<<512, 256>>>(ux, uy, uc, out);
}

// round 13
// speedup vs baseline: 1.5796x; 1.2365x over previous
#include <cuda_runtime.h>
#include <cstdint>

// QConv2d fused, register-resident merged transforms.
//   new_rho[(c,P),(c',P')] = sum_{e,e'} cc[c,e] cc[c',e'] A[(e,P),(e',P')]
//   cc[c,e]=uc[c,e+2],  A = (I2 (x) ux (x) uy) rho (same)^T.
// Phase 1: thread = (col, e). 64-row vector: GMEM -> regs -> kron(ux,uy) -> smem.
// Phase 2: thread = (row, e'). 64-col vector: smem -> regs -> kron(ux,uy) -> smem.
// Epilogue: read-once channel expansion, coalesced STG.128.
// Each phase is ONE batched load block + ONE long FMA stream (64-wide ILP),
// killing the serialized 29-cyc LDS chains that bounded every prior variant.

#define ST 132   // row stride (floats): 132 = 4*33 -> f4 phases conflict-free
#define NT 128

extern __shared__ float smf[];

__global__ __launch_bounds__(NT)
void qconv2d_kernel(const float* __restrict__ rho,
                    const float* __restrict__ ux,
                    const float* __restrict__ uy,
                    const float* __restrict__ uc,
                    float* __restrict__ out) {
    float* A   = smf;                    // 128 x 132 floats
    float* sux = smf + 128 * ST;         // 64
    float* suy = sux + 64;               // 64
    float* scc = suy + 64;               // 8: scc[c*2+e] = uc[c, e+2]

    const int t = threadIdx.x;
    const int b = blockIdx.x;

    if (t < 64) { sux[t] = ux[t]; suy[t] = uy[t]; }
    else if (t < 72) { int m = t - 64; scc[m] = uc[(m >> 1) * 4 + 2 + (m & 1)]; }
    __syncthreads();

    // ================= Phase 1: row transform (merged uy,ux) =================
    // task = (e, col): v[m] = rho[b, e*64+m, col]; v <- kron(ux,uy) v; A[e*64+m][col] = v[m].
#pragma unroll 1
    for (int it = 0; it < 2; it++) {
        const int task = t + NT * it;
        const int col = task & 127, e = task >> 7;
        const float* rb = rho + (size_t)b * 16384 + (size_t)(e * 64) * 128 + col;
        float v[64], w[64];
#pragma unroll
        for (int m = 0; m < 64; m++) v[m] = rb[(size_t)m * 128];   // coalesced LDG.32
        // stage uy (over j): w[i*8+k] = sum_j suy[k,j] * v[i*8+j]
#pragma unroll
        for (int k = 0; k < 8; k++)
#pragma unroll
            for (int j = 0; j < 8; j++) {
                const float cf = suy[k * 8 + j];
#pragma unroll
                for (int i = 0; i < 8; i++) {
                    if (j == 0) w[i * 8 + k] = cf * v[i * 8 + j];
                    else        w[i * 8 + k] = fmaf(cf, v[i * 8 + j], w[i * 8 + k]);
                }
            }
        // stage ux (over i): v[ki*8+kj] = sum_i sux[ki,i] * w[i*8+kj]
#pragma unroll
        for (int ki = 0; ki < 8; ki++)
#pragma unroll
            for (int i = 0; i < 8; i++) {
                const float cf = sux[ki * 8 + i];
#pragma unroll
                for (int kj = 0; kj < 8; kj++) {
                    if (i == 0) v[ki * 8 + kj] = cf * w[i * 8 + kj];
                    else        v[ki * 8 + kj] = fmaf(cf, w[i * 8 + kj], v[ki * 8 + kj]);
                }
            }
#pragma unroll
        for (int m = 0; m < 64; m++) A[(e * 64 + m) * ST + col] = v[m];  // conflict-free STS
    }
    __syncthreads();

    // ================= Phase 2: column transform (merged uy,ux) =================
    // task = (e', row): v[m] = A[r][e2*64+m]; v <- kron(ux,uy) v; A[r][e2*64+m] = v[m].
#pragma unroll 1
    for (int it = 0; it < 2; it++) {
        const int task = t + NT * it;
        const int r = task & 127, e2 = task >> 7;
        const int base = r * ST + e2 * 64;
        float v[64], w[64];
#pragma unroll
        for (int m = 0; m < 16; m++)
            *(float4*)&v[4 * m] = *(float4*)&A[base + 4 * m];    // conflict-free LDS.128
#pragma unroll
        for (int k = 0; k < 8; k++)
#pragma unroll
            for (int j = 0; j < 8; j++) {
                const float cf = suy[k * 8 + j];
#pragma unroll
                for (int i = 0; i < 8; i++) {
                    if (j == 0) w[i * 8 + k] = cf * v[i * 8 + j];
                    else        w[i * 8 + k] = fmaf(cf, v[i * 8 + j], w[i * 8 + k]);
                }
            }
#pragma unroll
        for (int ki = 0; ki < 8; ki++)
#pragma unroll
            for (int i = 0; i < 8; i++) {
                const float cf = sux[ki * 8 + i];
#pragma unroll
                for (int kj = 0; kj < 8; kj++) {
                    if (i == 0) v[ki * 8 + kj] = cf * w[i * 8 + kj];
                    else        v[ki * 8 + kj] = fmaf(cf, w[i * 8 + kj], v[ki * 8 + kj]);
                }
            }
#pragma unroll
        for (int m = 0; m < 16; m++)
            *(float4*)&A[base + 4 * m] = *(float4*)&v[4 * m];    // conflict-free STS.128
    }
    __syncthreads();

    // ================= Epilogue: read-once channel expansion =================
    const float c00 = scc[0], c01 = scc[1], c10 = scc[2], c11 = scc[3];
    const float c20 = scc[4], c21 = scc[5], c30 = scc[6], c31 = scc[7];
#pragma unroll 1
    for (int it = 0; it < 8; it++) {
        const int task = t + NT * it;
        const int q = task & 15, P = task >> 4;      // q: col quad 0..15, P: 0..63
        float4 a00 = *(float4*)&A[P * ST + 4 * q];
        float4 a01 = *(float4*)&A[P * ST + 64 + 4 * q];
        float4 a10 = *(float4*)&A[(64 + P) * ST + 4 * q];
        float4 a11 = *(float4*)&A[(64 + P) * ST + 64 + 4 * q];
        float* ob = out + (size_t)b * 65536 + (size_t)P * 256 + 4 * q;
#pragma unroll
        for (int cp = 0; cp < 4; cp++) {
            const float k0 = scc[2 * cp], k1 = scc[2 * cp + 1];
            float4 v0, v1, wv;
            v0.x = fmaf(k1, a01.x, k0 * a00.x); v0.y = fmaf(k1, a01.y, k0 * a00.y);
            v0.z = fmaf(k1, a01.z, k0 * a00.z); v0.w = fmaf(k1, a01.w, k0 * a00.w);
            v1.x = fmaf(k1, a11.x, k0 * a10.x); v1.y = fmaf(k1, a11.y, k0 * a10.y);
            v1.z = fmaf(k1, a11.z, k0 * a10.z); v1.w = fmaf(k1, a11.w, k0 * a10.w);
            wv.x = fmaf(c01, v1.x, c00 * v0.x); wv.y = fmaf(c01, v1.y, c00 * v0.y);
            wv.z = fmaf(c01, v1.z, c00 * v0.z); wv.w = fmaf(c01, v1.w, c00 * v0.w);
            *(float4*)(ob + (size_t)(0 * 64) * 256 + cp * 64) = wv;
            wv.x = fmaf(c11, v1.x, c10 * v0.x); wv.y = fmaf(c11, v1.y, c10 * v0.y);
            wv.z = fmaf(c11, v1.z, c10 * v0.z); wv.w = fmaf(c11, v1.w, c10 * v0.w);
            *(float4*)(ob + (size_t)(1 * 64) * 256 + cp * 64) = wv;
            wv.x = fmaf(c21, v1.x, c20 * v0.x); wv.y = fmaf(c21, v1.y, c20 * v0.y);
            wv.z = fmaf(c21, v1.z, c20 * v0.z); wv.w = fmaf(c21, v1.w, c20 * v0.w);
            *(float4*)(ob + (size_t)(2 * 64) * 256 + cp * 64) = wv;
            wv.x = fmaf(c31, v1.x, c30 * v0.x); wv.y = fmaf(c31, v1.y, c30 * v0.y);
            wv.z = fmaf(c31, v1.z, c30 * v0.z); wv.w = fmaf(c31, v1.w, c30 * v0.w);
            *(float4*)(ob + (size_t)(3 * 64) * 256 + cp * 64) = wv;
        }
    }
}

extern "C" void kernel_launch(void* const* d_in, const int* in_sizes, int n_in,
                              void* d_out, int out_size) {
    const float* rho = (const float*)d_in[0];   // [256,128,128]
    const float* ux  = (const float*)d_in[1];   // [8,8]
    const float* uy  = (const float*)d_in[2];   // [8,8]
    const float* uc  = (const float*)d_in[3];   // [4,4]
    float* out = (float*)d_out;                 // [256,256,256]

    const size_t smem = (128 * ST + 64 + 64 + 8) * sizeof(float);  // ~68.1 KB
    cudaFuncSetAttribute(qconv2d_kernel,
                         cudaFuncAttributeMaxDynamicSharedMemorySize, (int)smem);
    qconv2d_kernel<<<256, NT, smem>>>(rho, ux, uy, uc, out);
}

// round 14
// speedup vs baseline: 1.6295x; 1.0316x over previous
#include <cuda_runtime.h>
#include <cstdint>

// QConv2d fused, register-resident merged transforms, low-reg variant.
//   new_rho[(c,P),(c',P')] = sum_{e,e'} cc[c,e] cc[c',e'] A[(e,P),(e',P')]
//   cc[c,e]=uc[c,e+2],  A = (I2 (x) ux (x) uy) rho (same)^T.
// Phase 1: thread = (e, col): 64-row vector GMEM->regs, kron(ux,uy), ->smem.
// Phase 2: thread = (e', row): 64-col vector smem->regs, kron(ux,uy), ->smem.
// Register economy: uy stage in-place per octet (8-reg temp); ux stage
// accumulates one output octet at a time and stores it immediately.
// NT=256, __launch_bounds__(256,2) -> 2 CTAs/SM, 16 warps resident.

#define ST 132   // row stride (floats): f4 phases conflict-free (33 odd)
#define NT 256

extern __shared__ float smf[];

__global__ __launch_bounds__(NT, 2)
void qconv2d_kernel(const float* __restrict__ rho,
                    const float* __restrict__ ux,
                    const float* __restrict__ uy,
                    const float* __restrict__ uc,
                    float* __restrict__ out) {
    float* A   = smf;                    // 128 x 132 floats
    float* sux = smf + 128 * ST;         // 64
    float* suy = sux + 64;               // 64
    float* scc = suy + 64;               // 8: scc[c*2+e] = uc[c, e+2]

    const int t = threadIdx.x;
    const int b = blockIdx.x;

    if (t < 64) { sux[t] = ux[t]; suy[t] = uy[t]; }
    else if (t < 72) { int m = t - 64; scc[m] = uc[(m >> 1) * 4 + 2 + (m & 1)]; }
    __syncthreads();

    // ================= Phase 1: row transform (merged uy,ux) =================
    {
        const int col = t & 127, e = t >> 7;
        const float* rb = rho + (size_t)b * 16384 + (size_t)(e * 64) * 128 + col;
        float v[64];
#pragma unroll
        for (int m = 0; m < 64; m++) v[m] = rb[(size_t)m * 128];   // coalesced LDG
        // uy stage, in place per octet: v[i*8+k] <- sum_j suy[k,j] v[i*8+j]
#pragma unroll
        for (int i = 0; i < 8; i++) {
            float w[8];
#pragma unroll
            for (int k = 0; k < 8; k++) {
                float acc = suy[k * 8] * v[i * 8];
#pragma unroll
                for (int j = 1; j < 8; j++) acc = fmaf(suy[k * 8 + j], v[i * 8 + j], acc);
                w[k] = acc;
            }
#pragma unroll
            for (int k = 0; k < 8; k++) v[i * 8 + k] = w[k];
        }
        // ux stage, one output octet at a time -> STS immediately
#pragma unroll
        for (int ki = 0; ki < 8; ki++) {
            float acc[8];
            {
                const float cf = sux[ki * 8];
#pragma unroll
                for (int kj = 0; kj < 8; kj++) acc[kj] = cf * v[kj];
            }
#pragma unroll
            for (int i = 1; i < 8; i++) {
                const float cf = sux[ki * 8 + i];
#pragma unroll
                for (int kj = 0; kj < 8; kj++) acc[kj] = fmaf(cf, v[i * 8 + kj], acc[kj]);
            }
#pragma unroll
            for (int kj = 0; kj < 8; kj++)
                A[(e * 64 + ki * 8 + kj) * ST + col] = acc[kj];    // conflict-free STS
        }
    }
    __syncthreads();

    // ================= Phase 2: column transform (merged uy,ux) =================
    {
        const int r = t & 127, e2 = t >> 7;
        const int base = r * ST + e2 * 64;
        float v[64];
#pragma unroll
        for (int m = 0; m < 16; m++)
            *(float4*)&v[4 * m] = *(float4*)&A[base + 4 * m];      // LDS.128 c-free
#pragma unroll
        for (int i = 0; i < 8; i++) {
            float w[8];
#pragma unroll
            for (int k = 0; k < 8; k++) {
                float acc = suy[k * 8] * v[i * 8];
#pragma unroll
                for (int j = 1; j < 8; j++) acc = fmaf(suy[k * 8 + j], v[i * 8 + j], acc);
                w[k] = acc;
            }
#pragma unroll
            for (int k = 0; k < 8; k++) v[i * 8 + k] = w[k];
        }
#pragma unroll
        for (int ki = 0; ki < 8; ki++) {
            float acc[8];
            {
                const float cf = sux[ki * 8];
#pragma unroll
                for (int kj = 0; kj < 8; kj++) acc[kj] = cf * v[kj];
            }
#pragma unroll
            for (int i = 1; i < 8; i++) {
                const float cf = sux[ki * 8 + i];
#pragma unroll
                for (int kj = 0; kj < 8; kj++) acc[kj] = fmaf(cf, v[i * 8 + kj], acc[kj]);
            }
            *(float4*)&A[base + ki * 8]     = make_float4(acc[0], acc[1], acc[2], acc[3]);
            *(float4*)&A[base + ki * 8 + 4] = make_float4(acc[4], acc[5], acc[6], acc[7]);
        }
    }
    __syncthreads();

    // ================= Epilogue: read-once channel expansion =================
    const float c00 = scc[0], c01 = scc[1], c10 = scc[2], c11 = scc[3];
    const float c20 = scc[4], c21 = scc[5], c30 = scc[6], c31 = scc[7];
#pragma unroll 1
    for (int it = 0; it < 4; it++) {
        const int task = t + NT * it;
        const int q = task & 15, P = task >> 4;      // q: col quad 0..15, P: 0..63
        float4 a00 = *(float4*)&A[P * ST + 4 * q];
        float4 a01 = *(float4*)&A[P * ST + 64 + 4 * q];
        float4 a10 = *(float4*)&A[(64 + P) * ST + 4 * q];
        float4 a11 = *(float4*)&A[(64 + P) * ST + 64 + 4 * q];
        float* ob = out + (size_t)b * 65536 + (size_t)P * 256 + 4 * q;
#pragma unroll
        for (int cp = 0; cp < 4; cp++) {
            const float k0 = scc[2 * cp], k1 = scc[2 * cp + 1];
            float4 v0, v1, wv;
            v0.x = fmaf(k1, a01.x, k0 * a00.x); v0.y = fmaf(k1, a01.y, k0 * a00.y);
            v0.z = fmaf(k1, a01.z, k0 * a00.z); v0.w = fmaf(k1, a01.w, k0 * a00.w);
            v1.x = fmaf(k1, a11.x, k0 * a10.x); v1.y = fmaf(k1, a11.y, k0 * a10.y);
            v1.z = fmaf(k1, a11.z, k0 * a10.z); v1.w = fmaf(k1, a11.w, k0 * a10.w);
            wv.x = fmaf(c01, v1.x, c00 * v0.x); wv.y = fmaf(c01, v1.y, c00 * v0.y);
            wv.z = fmaf(c01, v1.z, c00 * v0.z); wv.w = fmaf(c01, v1.w, c00 * v0.w);
            *(float4*)(ob + (size_t)(0 * 64) * 256 + cp * 64) = wv;
            wv.x = fmaf(c11, v1.x, c10 * v0.x); wv.y = fmaf(c11, v1.y, c10 * v0.y);
            wv.z = fmaf(c11, v1.z, c10 * v0.z); wv.w = fmaf(c11, v1.w, c10 * v0.w);
            *(float4*)(ob + (size_t)(1 * 64) * 256 + cp * 64) = wv;
            wv.x = fmaf(c21, v1.x, c20 * v0.x); wv.y = fmaf(c21, v1.y, c20 * v0.y);
            wv.z = fmaf(c21, v1.z, c20 * v0.z); wv.w = fmaf(c21, v1.w, c20 * v0.w);
            *(float4*)(ob + (size_t)(2 * 64) * 256 + cp * 64) = wv;
            wv.x = fmaf(c31, v1.x, c30 * v0.x); wv.y = fmaf(c31, v1.y, c30 * v0.y);
            wv.z = fmaf(c31, v1.z, c30 * v0.z); wv.w = fmaf(c31, v1.w, c30 * v0.w);
            *(float4*)(ob + (size_t)(3 * 64) * 256 + cp * 64) = wv;
        }
    }
}

extern "C" void kernel_launch(void* const* d_in, const int* in_sizes, int n_in,
                              void* d_out, int out_size) {
    const float* rho = (const float*)d_in[0];   // [256,128,128]
    const float* ux  = (const float*)d_in[1];   // [8,8]
    const float* uy  = (const float*)d_in[2];   // [8,8]
    const float* uc  = (const float*)d_in[3];   // [4,4]
    float* out = (float*)d_out;                 // [256,256,256]

    const size_t smem = (128 * ST + 64 + 64 + 8) * sizeof(float);  // ~68.1 KB
    cudaFuncSetAttribute(qconv2d_kernel,
                         cudaFuncAttributeMaxDynamicSharedMemorySize, (int)smem);
    qconv2d_kernel<<<256, NT, smem>>>(rho, ux, uy, uc, out);
}